// round 5
// baseline (speedup 1.0000x reference)
#include <cuda_runtime.h>
#include <stdint.h>

#define N        4096
#define B        8
#define NITER    4
#define KCHUNKS  64
#define CHUNK    (N / KCHUNKS)   // 64
#define ABLOCK   256

// Persistent device scratch (no allocations allowed in kernel_launch).
__device__ __align__(16) float g_pred[2][B * N];                 // ping-pong iteration state
__device__ __align__(16) float g_partial[(size_t)KCHUNKS * N * B]; // split-K partial products
__device__ unsigned char g_mask[B * N];                          // seed mask

// ---------- packed f32x2 helpers (Blackwell) ----------
__device__ __forceinline__ uint64_t pack2(float x) {
    uint64_t r;
    asm("mov.b64 %0, {%1, %1};" : "=l"(r) : "f"(x));
    return r;
}
__device__ __forceinline__ uint64_t fma2(uint64_t a, uint64_t b, uint64_t c) {
    uint64_t d;
    asm("fma.rn.f32x2 %0, %1, %2, %3;" : "=l"(d) : "l"(a), "l"(b), "l"(c));
    return d;
}
__device__ __forceinline__ uint64_t mul2(uint64_t a, uint64_t b) {
    uint64_t d;
    asm("mul.rn.f32x2 %0, %1, %2;" : "=l"(d) : "l"(a), "l"(b));
    return d;
}

// ---------- setup kernels ----------
__global__ void mask_zero_kernel() {
    int t = blockIdx.x * blockDim.x + threadIdx.x;
    if (t < B * N) g_mask[t] = 0;
}

__global__ void seed_set_kernel(const int* __restrict__ seed, int ns) {
    int t = blockIdx.x * blockDim.x + threadIdx.x;
    if (t < ns) {
        int b = seed[2 * t];
        int n = seed[2 * t + 1];
        g_mask[b * N + n] = 1;
    }
}

// ---------- split-K partial-product kernel ----------
// grid: (N/ABLOCK, KCHUNKS); each thread owns one output column `a` and
// accumulates the product over CHUNK b-values for all 8 batches (4 packed pairs).
__global__ void __launch_bounds__(ABLOCK)
partial_kernel(const float* __restrict__ pred, const float* __restrict__ P) {
    __shared__ __align__(16) float s_np[CHUNK][B];   // negated pred chunk, [b_local][batch]

    const int a  = blockIdx.x * ABLOCK + threadIdx.x;
    const int c0 = blockIdx.y * CHUNK;

    // Stage -pred[i, c0 .. c0+CHUNK) into shared (coalesced global reads per batch row).
    for (int idx = threadIdx.x; idx < CHUNK * B; idx += ABLOCK) {
        int i  = idx / CHUNK;
        int bl = idx % CHUNK;
        s_np[bl][i] = -pred[i * N + c0 + bl];
    }
    __syncthreads();

    const uint64_t ONE2 = 0x3F8000003F800000ULL;   // packed (1.0f, 1.0f)
    uint64_t pr0 = ONE2, pr1 = ONE2, pr2 = ONE2, pr3 = ONE2;

    const float* Pcol = P + (size_t)c0 * N + a;

#pragma unroll 8
    for (int bl = 0; bl < CHUNK; ++bl) {
        float p = __ldg(Pcol + (size_t)bl * N);        // coalesced across lanes
        uint64_t p2 = pack2(p);
        const ulonglong2* row = reinterpret_cast<const ulonglong2*>(&s_np[bl][0]);
        ulonglong2 np01 = row[0];   // batches (0,1) and (2,3)
        ulonglong2 np23 = row[1];   // batches (4,5) and (6,7)
        pr0 = mul2(pr0, fma2(p2, np01.x, ONE2));       // prod *= (1 - p*pred)
        pr1 = mul2(pr1, fma2(p2, np01.y, ONE2));
        pr2 = mul2(pr2, fma2(p2, np23.x, ONE2));
        pr3 = mul2(pr3, fma2(p2, np23.y, ONE2));
    }

    ulonglong2* outp = reinterpret_cast<ulonglong2*>(
        &g_partial[((size_t)blockIdx.y * N + a) * B]);
    outp[0] = make_ulonglong2(pr0, pr1);
    outp[1] = make_ulonglong2(pr2, pr3);
}

// ---------- combine kernel: multiply partials, 1-prod, seed clamp ----------
__global__ void combine_kernel(float* __restrict__ out) {
    int t = blockIdx.x * blockDim.x + threadIdx.x;   // 0 .. B*N-1
    if (t >= B * N) return;
    int a = t >> 3;
    int i = t & 7;

    float prod = 1.0f;
#pragma unroll
    for (int c = 0; c < KCHUNKS; ++c)
        prod *= g_partial[((size_t)c * N + a) * B + i];

    float v = 1.0f - prod;
    if (g_mask[i * N + a]) v = 1.0f;
    out[i * N + a] = v;
}

extern "C" void kernel_launch(void* const* d_in, const int* in_sizes, int n_in,
                              void* d_out, int out_size) {
    const float* preds = (const float*)d_in[0];   // [B, N] f32
    const float* P     = (const float*)d_in[1];   // [N, N] f32
    const int*   seed  = (const int*)d_in[2];     // [NSEEDS, 2] i32
    int nseeds = in_sizes[2] / 2;
    float* out = (float*)d_out;                   // [B, N] f32

    float* gpred = nullptr;
    cudaGetSymbolAddress((void**)&gpred, g_pred); // pure lookup; capture-safe
    float* buf0 = gpred;
    float* buf1 = gpred + B * N;

    // seed mask (rebuilt every call -> deterministic)
    mask_zero_kernel<<<(B * N + 255) / 256, 256>>>();
    seed_set_kernel<<<(nseeds + 127) / 128, 128>>>(seed, nseeds);

    dim3 pgrid(N / ABLOCK, KCHUNKS);
    const float* src = preds;
    float* bufs[2] = {buf0, buf1};
    for (int it = 0; it < NITER; ++it) {
        partial_kernel<<<pgrid, ABLOCK>>>(src, P);
        float* dst = (it == NITER - 1) ? out : bufs[it & 1];
        combine_kernel<<<(B * N + 255) / 256, 256>>>(dst);
        src = dst;
    }
}